// round 1
// baseline (speedup 1.0000x reference)
#include <cuda_runtime.h>
#include <cstdint>
#include <math.h>

// Problem constants
#define BB 4
#define NN 2048
#define KK 32
#define DD 256
#define TT 256
#define HH 4
#define NTOK (BB*NN)          // 8192
#define NROWS (NTOK*KK)       // 262144

// Scratch (static __device__ — no allocations allowed)
__device__ float g_Wf[256*256];       // W_ego @ W_h_bot
__device__ float g_biasc[256];        // b_h + b_ego @ W_h_bot
__device__ float g_ego[NTOK*256];     // ego_ctx @ g_Wf + g_biasc
__device__ float g_logits[NROWS*4];
__device__ int   g_mask_is_byte;

__device__ __forceinline__ float wsum(float v){
    #pragma unroll
    for (int o = 16; o; o >>= 1) v += __shfl_xor_sync(0xffffffffu, v, o);
    return v;
}
__device__ __forceinline__ float wmax(float v){
    #pragma unroll
    for (int o = 16; o; o >>= 1) v = fmaxf(v, __shfl_xor_sync(0xffffffffu, v, o));
    return v;
}
__device__ __forceinline__ float fast_tanh(float x){
    float y;
    asm("tanh.approx.f32 %0, %1;" : "=f"(y) : "f"(x));
    return y;
}
__device__ __forceinline__ float gelu_tanh(float x){
    float x3 = x * x * x;
    return 0.5f * x * (1.0f + fast_tanh(0.7978845608028654f * fmaf(0.044715f, x3, x)));
}

// ---------------------------------------------------------------------------
// Detect mask element width: 1-byte (bool) vs 4-byte (int32/float32).
// For 4-byte 0/1 values, bytes at (i%4)!=0 are all zero; for random byte
// bools ~half are nonzero. Reading 262144 bytes is in-bounds either way.
// ---------------------------------------------------------------------------
__global__ void k_detect(const unsigned char* __restrict__ m, int nbytes){
    __shared__ int f;
    if (threadIdx.x == 0) f = 0;
    __syncthreads();
    int loc = 0;
    for (int i = threadIdx.x; i < nbytes; i += blockDim.x)
        if ((i & 3) && m[i]) loc = 1;
    if (loc) atomicOr(&f, 1);
    __syncthreads();
    if (threadIdx.x == 0) g_mask_is_byte = f;
}

// ---------------------------------------------------------------------------
// W_fused[e][j] = sum_t W_ego[e][t] * W_h[256+t][j]
// ---------------------------------------------------------------------------
__global__ void k_fuse_w(const float* __restrict__ We, const float* __restrict__ Wh){
    __shared__ float s[256];
    int e = blockIdx.x, j = threadIdx.x;
    s[j] = We[e*256 + j];
    __syncthreads();
    float acc = 0.f;
    #pragma unroll 4
    for (int t = 0; t < 256; t++)
        acc = fmaf(s[t], Wh[(256+t)*256 + j], acc);
    g_Wf[e*256 + j] = acc;
}

__global__ void k_fuse_b(const float* __restrict__ be, const float* __restrict__ bh,
                         const float* __restrict__ Wh){
    __shared__ float s[256];
    int j = threadIdx.x;
    s[j] = be[j];
    __syncthreads();
    float acc = bh[j];
    #pragma unroll 4
    for (int t = 0; t < 256; t++)
        acc = fmaf(s[t], Wh[(256+t)*256 + j], acc);
    g_biasc[j] = acc;
}

// ---------------------------------------------------------------------------
// ego_contrib[row][j] = sum_e ego_ctx[row][e] * Wf[e][j] + biasc[j]
// 16 rows per block, 256 threads (thread = output column j).
// ---------------------------------------------------------------------------
__global__ void __launch_bounds__(256) k_ego(const float* __restrict__ ego){
    __shared__ float s[16*256];
    int tid = threadIdx.x;
    int row0 = blockIdx.x * 16;
    const float4* src = (const float4*)(ego + (size_t)row0 * 256);
    float4* d4 = (float4*)s;
    #pragma unroll
    for (int q = 0; q < 4; q++) d4[tid + q*256] = src[tid + q*256];
    __syncthreads();
    float acc[16];
    #pragma unroll
    for (int r = 0; r < 16; r++) acc[r] = 0.f;
    for (int e = 0; e < 256; e++){
        float w = g_Wf[e*256 + tid];
        #pragma unroll
        for (int r = 0; r < 16; r++)
            acc[r] = fmaf(s[r*256 + e], w, acc[r]);
    }
    float bb = g_biasc[tid];
    #pragma unroll
    for (int r = 0; r < 16; r++)
        g_ego[(size_t)(row0 + r)*256 + tid] = acc[r] + bb;
}

// ---------------------------------------------------------------------------
// Main fused kernel: block = one (b,n) token (32 rows).
//  1) LN(inv_tok) -> smem A panel (32x256)
//  2) C[32,256] = A @ W_h_top  (BK=8 tiles, 4x8 microtile per thread)
//  3) epilogue: + ego_contrib, gelu, logits = g @ W_logit, warp-reduce, store
// Thread map: lane covers cols {lane*4..+3, 128+lane*4..+3}, warp covers rows
// wid*4..+3  (8 warps x 4 rows = 32 rows).
// ---------------------------------------------------------------------------
__global__ void __launch_bounds__(256) k_main(const float* __restrict__ inv,
                                              const float* __restrict__ Wh,
                                              const float* __restrict__ lns,
                                              const float* __restrict__ lnb,
                                              const float* __restrict__ Wl){
    __shared__ float As[32*256];   // 32 KB
    __shared__ float Bs[8*256];    // 8 KB
    __shared__ float Wls[256*4];   // 4 KB
    int tid = threadIdx.x, lane = tid & 31, wid = tid >> 5;
    for (int i = tid; i < 1024; i += 256) Wls[i] = Wl[i];

    int token = blockIdx.x;
    size_t rowbase = (size_t)token * 32;

    // LayerNorm scale/bias for this lane's 8-element slice (d0 = lane*8)
    const float4* lns4 = (const float4*)lns;
    const float4* lnb4 = (const float4*)lnb;
    float4 sc0 = lns4[lane*2], sc1 = lns4[lane*2 + 1];
    float4 sb0 = lnb4[lane*2], sb1 = lnb4[lane*2 + 1];

    // LN pre-pass: warp handles rows wid*4..wid*4+3
    for (int rr = 0; rr < 4; rr++){
        int row = wid*4 + rr;
        const float4* src = (const float4*)(inv + (rowbase + row)*256);
        float4 v0 = src[lane*2];
        float4 v1 = src[lane*2 + 1];
        float s = v0.x+v0.y+v0.z+v0.w + v1.x+v1.y+v1.z+v1.w;
        float q = v0.x*v0.x+v0.y*v0.y+v0.z*v0.z+v0.w*v0.w
                + v1.x*v1.x+v1.y*v1.y+v1.z*v1.z+v1.w*v1.w;
        s = wsum(s); q = wsum(q);
        float mean = s * (1.f/256.f);
        float var  = q * (1.f/256.f) - mean*mean;
        float rstd = rsqrtf(var + 1e-6f);
        float4 o0, o1;
        o0.x = (v0.x-mean)*rstd*sc0.x + sb0.x;
        o0.y = (v0.y-mean)*rstd*sc0.y + sb0.y;
        o0.z = (v0.z-mean)*rstd*sc0.z + sb0.z;
        o0.w = (v0.w-mean)*rstd*sc0.w + sb0.w;
        o1.x = (v1.x-mean)*rstd*sc1.x + sb1.x;
        o1.y = (v1.y-mean)*rstd*sc1.y + sb1.y;
        o1.z = (v1.z-mean)*rstd*sc1.z + sb1.z;
        o1.w = (v1.w-mean)*rstd*sc1.w + sb1.w;
        float4* dst = (float4*)(As + row*256);
        dst[lane*2]     = o0;
        dst[lane*2 + 1] = o1;
    }
    __syncthreads();

    float acc[4][8];
    #pragma unroll
    for (int i = 0; i < 4; i++)
        #pragma unroll
        for (int j = 0; j < 8; j++) acc[i][j] = 0.f;

    int r0 = wid * 4;
    for (int kk = 0; kk < 256; kk += 8){
        const float4* gB = (const float4*)(Wh + kk*256);
        float4* sB = (float4*)Bs;
        sB[tid]       = gB[tid];
        sB[tid + 256] = gB[tid + 256];
        __syncthreads();
        #pragma unroll
        for (int k = 0; k < 8; k++){
            float a0 = As[(r0+0)*256 + kk + k];
            float a1 = As[(r0+1)*256 + kk + k];
            float a2 = As[(r0+2)*256 + kk + k];
            float a3 = As[(r0+3)*256 + kk + k];
            float4 b0 = *(const float4*)(Bs + k*256 + lane*4);
            float4 b1 = *(const float4*)(Bs + k*256 + 128 + lane*4);
            float bv[8] = {b0.x,b0.y,b0.z,b0.w,b1.x,b1.y,b1.z,b1.w};
            float av[4] = {a0,a1,a2,a3};
            #pragma unroll
            for (int i = 0; i < 4; i++)
                #pragma unroll
                for (int j = 0; j < 8; j++)
                    acc[i][j] = fmaf(av[i], bv[j], acc[i][j]);
        }
        __syncthreads();
    }

    // Epilogue: + ego_contrib, gelu, project to 4 logits
    const float* egorow = g_ego + (size_t)token * 256;
    float4 e0 = ((const float4*)egorow)[lane];
    float4 e1 = ((const float4*)(egorow + 128))[lane];
    float eg[8] = {e0.x,e0.y,e0.z,e0.w,e1.x,e1.y,e1.z,e1.w};

    float pl[4][4];
    #pragma unroll
    for (int i = 0; i < 4; i++)
        #pragma unroll
        for (int h = 0; h < 4; h++) pl[i][h] = 0.f;

    const float4* Wls4 = (const float4*)Wls;
    #pragma unroll
    for (int j = 0; j < 8; j++){
        int col = (j < 4) ? (lane*4 + j) : (128 + lane*4 + (j-4));
        float4 w = Wls4[col];
        #pragma unroll
        for (int i = 0; i < 4; i++){
            float g = gelu_tanh(acc[i][j] + eg[j]);
            pl[i][0] = fmaf(g, w.x, pl[i][0]);
            pl[i][1] = fmaf(g, w.y, pl[i][1]);
            pl[i][2] = fmaf(g, w.z, pl[i][2]);
            pl[i][3] = fmaf(g, w.w, pl[i][3]);
        }
    }

    // Reduce the 16 (row,head) partial sums across the warp's 32 lanes
    float outv = 0.f;
    #pragma unroll
    for (int p = 0; p < 16; p++){
        float v = pl[p >> 2][p & 3];
        #pragma unroll
        for (int o = 16; o; o >>= 1) v += __shfl_xor_sync(0xffffffffu, v, o);
        if (lane == p) outv = v;
    }
    if (lane < 16)
        g_logits[(rowbase + r0 + (lane >> 2))*4 + (lane & 3)] = outv;
}

// ---------------------------------------------------------------------------
// Masked softmax over K (axis=-2) per head + alpha-weighted r/u reductions.
// warp = one token, lane = k. 8 tokens per block.
// ---------------------------------------------------------------------------
__global__ void __launch_bounds__(256) k_final(const float* __restrict__ r,
                                               const float* __restrict__ u,
                                               const void* __restrict__ mask,
                                               float* __restrict__ out){
    int tid = threadIdx.x, lane = tid & 31, w = tid >> 5;
    int T = blockIdx.x * 8 + w;
    size_t row = (size_t)T * 32 + lane;

    float4 l4 = ((const float4*)g_logits)[row];
    float l[4] = {l4.x, l4.y, l4.z, l4.w};

    bool m;
    if (g_mask_is_byte) m = ((const unsigned char*)mask)[row] != 0;
    else                m = ((const unsigned int*)mask)[row] != 0u;

    float a[4];
    #pragma unroll
    for (int h = 0; h < 4; h++){
        float v = m ? l[h] : -3.402823466e38f;
        float mx = wmax(v);
        float e  = m ? __expf(l[h] - mx) : 0.f;
        float s  = wsum(e);
        a[h] = (s > 0.f) ? (e / s) : 0.f;
    }

    // alpha output: base offset = 2 * (NTOK*12)
    float* alpha_out = out + 2 * (NTOK * 12);
    ((float4*)alpha_out)[row] = make_float4(a[0], a[1], a[2], a[3]);

    float rr[3], uu[3];
    #pragma unroll
    for (int d = 0; d < 3; d++){
        rr[d] = r[row*3 + d];
        uu[d] = u[row*3 + d];
    }

    float orv = 0.f, ouv = 0.f;
    #pragma unroll
    for (int p = 0; p < 12; p++){
        float v1 = a[p/3] * rr[p%3];
        float v2 = a[p/3] * uu[p%3];
        #pragma unroll
        for (int o = 16; o; o >>= 1){
            v1 += __shfl_xor_sync(0xffffffffu, v1, o);
            v2 += __shfl_xor_sync(0xffffffffu, v2, o);
        }
        if (lane == p) orv = v1;
        if (lane == p) ouv = v2;
    }
    if (lane < 12){
        out[(size_t)T*12 + lane]             = orv;              // v_r
        out[NTOK*12 + (size_t)T*12 + lane]   = ouv;              // v_u
    }
}

// ---------------------------------------------------------------------------
extern "C" void kernel_launch(void* const* d_in, const int* in_sizes, int n_in,
                              void* d_out, int out_size){
    (void)in_sizes; (void)n_in; (void)out_size;
    const float* inv  = (const float*)d_in[0];   // inv_tok (B,N,K,D)
    const float* ego  = (const float*)d_in[1];   // ego_ctx (B,N,256)
    const float* r    = (const float*)d_in[2];   // (B,N,K,3)
    const float* u    = (const float*)d_in[3];   // (B,N,K,3)
    const void*  mask = d_in[4];                 // (B,N,K) bool/int
    const float* We   = (const float*)d_in[5];   // W_ego (256,256)
    const float* be   = (const float*)d_in[6];   // b_ego (256)
    const float* lns  = (const float*)d_in[7];   // ln_scale (256)
    const float* lnb  = (const float*)d_in[8];   // ln_bias (256)
    const float* Wh   = (const float*)d_in[9];   // W_h (512,256)
    const float* bh   = (const float*)d_in[10];  // b_h (256)
    const float* Wl   = (const float*)d_in[11];  // W_logit (256,4)
    // d_in[12] = b_logit: constant per head over K -> softmax-invariant, unused.

    k_detect<<<1, 256>>>((const unsigned char*)mask, NROWS);
    k_fuse_w<<<256, 256>>>(We, Wh);
    k_fuse_b<<<1, 256>>>(be, bh, Wh);
    k_ego<<<NTOK/16, 256>>>(ego);
    k_main<<<NTOK, 256>>>(inv, Wh, lns, lnb, Wl);
    k_final<<<NTOK/8, 256>>>(r, u, mask, (float*)d_out);
}